// round 11
// baseline (speedup 1.0000x reference)
#include <cuda_runtime.h>
#include <cuda_fp16.h>
#include <cstdint>

#define NN   8192
#define FIN  256
#define FOUT 128
#define NC   128        // j-chunks of 64
#define BM   32         // rows per CTA in main kernel
#define GRID_MAIN (NN / BM)   // 256

// ---------------- scratch (static device globals; no allocation) ----------------
__device__ __align__(16) __half g_Wh16[(size_t)NN * FOUT];  // [row j][col c] fp16
__device__ __align__(16) float g_nf1[NN];   // -f1
__device__ __align__(16) float g_H1 [NN];   // exp(-0.8 f1)
__device__ __align__(16) float g_f2 [NN];
__device__ __align__(16) float g_E2 [NN];   // exp(f2)
__device__ __align__(16) float g_G2 [NN];   // exp(0.2 f2)

__device__ __forceinline__ uint32_t sptr(const void* p) {
    return (uint32_t)__cvta_generic_to_shared(p);
}

// =====================================================================
// Kernel 1: Wh = h @ W (fp32 SIMT GEMM), cp.async double-buffered.
// Fused fp16 output + f1/f2 reductions + exp vectors. (unchanged R10)
// =====================================================================
__global__ __launch_bounds__(256, 2) void wh_gemm_kernel(
    const float* __restrict__ h, const float* __restrict__ Wm,
    const float* __restrict__ a)
{
    __shared__ float hs[2][32][36];
    __shared__ float Ws[2][32][132];
    const int tid = threadIdx.x;
    const int i0  = blockIdx.x * 32;
    const int ty  = tid >> 4, tx = tid & 15;

    auto stage = [&](int kt) {
        int k0 = kt * 32, buf = kt & 1;
        {   int r = tid >> 3, c = (tid & 7) * 4;
            asm volatile("cp.async.cg.shared.global [%0],[%1],16;\n"
                :: "r"(sptr(&hs[buf][r][c])),
                   "l"(&h[(size_t)(i0 + r) * FIN + k0 + c]));
        }
        {   int r = tid >> 3, c = (tid & 7) * 16;
#pragma unroll
            for (int q = 0; q < 4; q++)
                asm volatile("cp.async.cg.shared.global [%0],[%1],16;\n"
                    :: "r"(sptr(&Ws[buf][r][c + 4*q])),
                       "l"(&Wm[(size_t)(k0 + r) * FOUT + c + 4*q]));
        }
        asm volatile("cp.async.commit_group;\n");
    };

    float acc[2][8];
#pragma unroll
    for (int u = 0; u < 2; u++)
#pragma unroll
        for (int v = 0; v < 8; v++) acc[u][v] = 0.0f;

    stage(0);
    for (int kt = 0; kt < 8; kt++) {
        asm volatile("cp.async.wait_group 0;\n");
        __syncthreads();
        if (kt < 7) stage(kt + 1);
        const int buf = kt & 1;
#pragma unroll 8
        for (int k = 0; k < 32; k++) {
            float a0 = hs[buf][2*ty][k], a1 = hs[buf][2*ty+1][k];
            float4 b0 = *(const float4*)&Ws[buf][k][8*tx];
            float4 b1 = *(const float4*)&Ws[buf][k][8*tx + 4];
            float bv[8] = {b0.x,b0.y,b0.z,b0.w,b1.x,b1.y,b1.z,b1.w};
#pragma unroll
            for (int v = 0; v < 8; v++) {
                acc[0][v] = fmaf(a0, bv[v], acc[0][v]);
                acc[1][v] = fmaf(a1, bv[v], acc[1][v]);
            }
        }
    }

    float f1a[2] = {0.f, 0.f}, f2a[2] = {0.f, 0.f};
#pragma unroll
    for (int u = 0; u < 2; u++) {
        int row = i0 + 2*ty + u;
#pragma unroll
        for (int q = 0; q < 4; q++) {
            *(__half2*)&g_Wh16[(size_t)row * FOUT + 8*tx + 2*q] =
                __floats2half2_rn(acc[u][2*q], acc[u][2*q+1]);
        }
#pragma unroll
        for (int v = 0; v < 8; v++) {
            int col = 8*tx + v;
            f1a[u] = fmaf(acc[u][v], a[col],        f1a[u]);
            f2a[u] = fmaf(acc[u][v], a[FOUT + col], f2a[u]);
        }
    }
#pragma unroll
    for (int o = 8; o > 0; o >>= 1) {
        f1a[0] += __shfl_xor_sync(0xffffffffu, f1a[0], o);
        f1a[1] += __shfl_xor_sync(0xffffffffu, f1a[1], o);
        f2a[0] += __shfl_xor_sync(0xffffffffu, f2a[0], o);
        f2a[1] += __shfl_xor_sync(0xffffffffu, f2a[1], o);
    }
    if (tx == 0) {
#pragma unroll
        for (int u = 0; u < 2; u++) {
            int i = i0 + 2*ty + u;
            float f1 = f1a[u], f2 = f2a[u];
            g_nf1[i] = -f1;
            g_H1[i]  = expf(-0.8f * f1);
            g_f2[i]  = f2;
            g_E2[i]  = expf(f2);
            g_G2[i]  = expf(0.2f * f2);
        }
    }
}

// =====================================================================
// Kernel 2: WARP-SPECIALIZED fused masked-softmax-attention.
// 512 threads: warps 0-7 = producers (adj ring + B staging + pgen),
// warps 8-15 = consumers (LDSM + HMMA, warp tile m16n32, 2m x 4n).
// 4-slot ring {P tile, B tile} guarded by full/empty mbarriers — ZERO
// __syncthreads in the main loop. Producer cp.async accounting is R10's
// proven [B(ch+2)][A(ch+3)] alternation + wait_group 4.
// Join at epilogue via named bar 1 (producers arrive, consumers sync).
// =====================================================================
__device__ __forceinline__ void mma_fp16(float* c, const uint32_t* a,
                                         uint32_t b0, uint32_t b1)
{
    asm volatile(
        "mma.sync.aligned.m16n8k16.row.col.f32.f16.f16.f32 "
        "{%0,%1,%2,%3},{%4,%5,%6,%7},{%8,%9},{%0,%1,%2,%3};\n"
        : "+f"(c[0]), "+f"(c[1]), "+f"(c[2]), "+f"(c[3])
        : "r"(a[0]), "r"(a[1]), "r"(a[2]), "r"(a[3]), "r"(b0), "r"(b1));
}

#define MBAR_INIT(addr, cnt) \
    asm volatile("mbarrier.init.shared.b64 [%0], %1;" :: "r"(addr), "r"(cnt) : "memory")
#define MBAR_ARRIVE(addr) \
    asm volatile("mbarrier.arrive.shared.b64 _, [%0];" :: "r"(addr) : "memory")
#define MBAR_WAIT(addr, ph) do {                                              \
    asm volatile("{\n\t.reg .pred P;\n\t"                                     \
        "WL%=:\n\t"                                                           \
        "mbarrier.try_wait.parity.acquire.cta.shared::cta.b64 P, [%0], %1, 0x989680;\n\t" \
        "@P bra WD%=;\n\tbra WL%=;\n\tWD%=:\n\t}"                             \
        :: "r"(addr), "r"(ph) : "memory"); } while (0)

#define SSLOT    4
#define ADJ_SLOT 8192u       // 32 x 64 ints
#define SP_SLOT  4608u       // 32 x 72 halfs (144B rows)
#define SB_SLOT  17408u      // 64 x 136 halfs (272B rows)
#define DYN_SMEM (3*ADJ_SLOT + SSLOT*SP_SLOT + SSLOT*SB_SLOT)   // 112640

__global__ __launch_bounds__(512, 2) void gat_main_kernel(
    const int* __restrict__ adj, float* __restrict__ out)
{
    extern __shared__ char dynsm[];
    __shared__ float sden[BM];
    __shared__ __align__(8) unsigned long long mbar[2 * SSLOT]; // full[0..3], empty[4..7]

    const int tid  = threadIdx.x;
    const int lane = tid & 31;
    const int warp = tid >> 5;     // 0..15
    const int i0   = blockIdx.x * BM;

    const uint32_t adjS = sptr(dynsm);
    const uint32_t spS  = adjS + 3 * ADJ_SLOT;
    const uint32_t sbS  = spS  + SSLOT * SP_SLOT;
    const uint32_t mbF  = sptr(&mbar[0]);
    const uint32_t mbE  = sptr(&mbar[SSLOT]);

    if (tid == 0) {
#pragma unroll
        for (int s = 0; s < SSLOT; s++) {
            MBAR_INIT(mbF + 8*s, 256);   // full: 256 producer arrivals
            MBAR_INIT(mbE + 8*s, 256);   // empty: 256 consumer arrivals
        }
    }
    __syncthreads();

    if (warp < 8) {
        // ================= PRODUCER (256 threads) =================
        const int r  = tid >> 3;     // 0..31 row
        const int cq = tid & 7;      // col group of 8
        const int* adjrow = &adj[(size_t)(i0 + r) * NN + 8 * cq];
        const float nf1r = g_nf1[i0 + r];
        const float H1r  = g_H1 [i0 + r];
        float den = 0.0f;

        auto stage_adj = [&](int ch) {   // self-consumed ring %3
            if (ch < NC) {
                uint32_t dst = adjS + (uint32_t)(ch % 3) * ADJ_SLOT
                             + (uint32_t)(r * 256 + 32 * cq);
                const int* src = adjrow + ch * 64;
                asm volatile("cp.async.cg.shared.global [%0],[%1],16;\n" :: "r"(dst), "l"(src));
                asm volatile("cp.async.cg.shared.global [%0],[%1],16;\n" :: "r"(dst+16u), "l"(src+4));
            }
            asm volatile("cp.async.commit_group;\n");
        };
        auto stage_B = [&](int ch) {     // only called with ch<NC, after empty-wait
            const int j0 = ch * 64;
            uint32_t base = sbS + (uint32_t)(ch & 3) * SB_SLOT;
#pragma unroll
            for (int i = 0; i < 4; i++) {
                int seg = tid + 256 * i;          // 0..1023
                int rr = seg >> 4, ss = seg & 15;
                const __half* src = &g_Wh16[(size_t)(j0 + rr) * FOUT + 8 * ss];
                uint32_t dst = base + (uint32_t)(rr * 272 + 16 * ss);
                asm volatile("cp.async.cg.shared.global [%0],[%1],16;\n" :: "r"(dst), "l"(src));
            }
        };
        auto pgen = [&](int ch) {
            const int j0 = ch * 64, c0 = 8 * cq;
            uint32_t aoff = adjS + (uint32_t)(ch % 3) * ADJ_SLOT
                          + (uint32_t)(r * 256 + 32 * cq);
            int4 a0, a1;
            asm volatile("ld.shared.v4.b32 {%0,%1,%2,%3},[%4];"
                         : "=r"(a0.x), "=r"(a0.y), "=r"(a0.z), "=r"(a0.w) : "r"(aoff));
            asm volatile("ld.shared.v4.b32 {%0,%1,%2,%3},[%4];"
                         : "=r"(a1.x), "=r"(a1.y), "=r"(a1.z), "=r"(a1.w) : "r"(aoff + 16u));
            float4 f2v0 = __ldg((const float4*)&g_f2[j0 + c0]);
            float4 f2v1 = __ldg((const float4*)&g_f2[j0 + c0 + 4]);
            float4 E2v0 = __ldg((const float4*)&g_E2[j0 + c0]);
            float4 E2v1 = __ldg((const float4*)&g_E2[j0 + c0 + 4]);
            float4 G2v0 = __ldg((const float4*)&g_G2[j0 + c0]);
            float4 G2v1 = __ldg((const float4*)&g_G2[j0 + c0 + 4]);
            float w0 = (a0.x > 0) ? ((f2v0.x > nf1r) ? E2v0.x : H1r * G2v0.x) : 0.0f;
            float w1 = (a0.y > 0) ? ((f2v0.y > nf1r) ? E2v0.y : H1r * G2v0.y) : 0.0f;
            float w2 = (a0.z > 0) ? ((f2v0.z > nf1r) ? E2v0.z : H1r * G2v0.z) : 0.0f;
            float w3 = (a0.w > 0) ? ((f2v0.w > nf1r) ? E2v0.w : H1r * G2v0.w) : 0.0f;
            float w4 = (a1.x > 0) ? ((f2v1.x > nf1r) ? E2v1.x : H1r * G2v1.x) : 0.0f;
            float w5 = (a1.y > 0) ? ((f2v1.y > nf1r) ? E2v1.y : H1r * G2v1.y) : 0.0f;
            float w6 = (a1.z > 0) ? ((f2v1.z > nf1r) ? E2v1.z : H1r * G2v1.z) : 0.0f;
            float w7 = (a1.w > 0) ? ((f2v1.w > nf1r) ? E2v1.w : H1r * G2v1.w) : 0.0f;
            __half2 p0 = __floats2half2_rn(w0, w1);
            __half2 p1 = __floats2half2_rn(w2, w3);
            __half2 p2 = __floats2half2_rn(w4, w5);
            __half2 p3 = __floats2half2_rn(w6, w7);
            // denominator from the SAME fp16-rounded weights the MMA sees
            den += __low2float(p0) + __high2float(p0) + __low2float(p1) + __high2float(p1)
                 + __low2float(p2) + __high2float(p2) + __low2float(p3) + __high2float(p3);
            uint32_t dst = spS + (uint32_t)(ch & 3) * SP_SLOT
                         + (uint32_t)(r * 144 + c0 * 2);
            asm volatile("st.shared.v4.b32 [%0],{%1,%2,%3,%4};"
                         :: "r"(dst), "r"(*(uint32_t*)&p0), "r"(*(uint32_t*)&p1),
                            "r"(*(uint32_t*)&p2), "r"(*(uint32_t*)&p3) : "memory");
        };

        // ---- prologue: commits [A0][B0][A1][B1][A2]; empty-waits pass (parity 1) ----
        stage_adj(0);
        MBAR_WAIT(mbE + 8*0, 1); stage_B(0);
        asm volatile("cp.async.commit_group;\n");
        stage_adj(1);
        MBAR_WAIT(mbE + 8*1, 1); stage_B(1);
        asm volatile("cp.async.commit_group;\n");
        stage_adj(2);
        asm volatile("cp.async.wait_group 4;\n");   // forces A0
        pgen(0);                                     // -> slot 0

        // empty-wait cursor: next slot 2, phase 1
        int eslot = 2, eph = 1;

        // ---- main loop ----
        for (int ch = 0; ch < NC; ch++) {
            if (ch + 2 < NC) {
                MBAR_WAIT(mbE + 8*eslot, eph);
                eslot++; if (eslot == SSLOT) { eslot = 0; eph ^= 1; }
                stage_B(ch + 2);
            }
            asm volatile("cp.async.commit_group;\n");
            stage_adj(ch + 3);
            asm volatile("cp.async.wait_group 4;\n");   // forces B(ch), A(ch+1)
            if (ch + 1 < NC) pgen(ch + 1);              // -> slot (ch+1)&3
            MBAR_ARRIVE(mbF + 8*(ch & 3));              // publish P(ch)+B(ch)
        }

        // ---- producer epilogue: denominator ----
        den += __shfl_xor_sync(0xffffffffu, den, 1);
        den += __shfl_xor_sync(0xffffffffu, den, 2);
        den += __shfl_xor_sync(0xffffffffu, den, 4);
        if (cq == 0) sden[r] = den;
        asm volatile("bar.arrive 1, 512;" ::: "memory");
    } else {
        // ================= CONSUMER (256 threads) =================
        const int cw = warp - 8;       // 0..7
        const int wm = cw & 1;         // m16 position
        const int wn = cw >> 1;        // n32 position
        const int mi = lane >> 3, l7 = lane & 7;

        float acc[4][4];
#pragma unroll
        for (int nf = 0; nf < 4; nf++)
#pragma unroll
            for (int q = 0; q < 4; q++) acc[nf][q] = 0.0f;

        int fph = 0;
        for (int ch = 0; ch < NC; ch++) {
            const int s = ch & 3;
            MBAR_WAIT(mbF + 8*s, fph);
            uint32_t sp = spS + (uint32_t)s * SP_SLOT;
            uint32_t sb = sbS + (uint32_t)s * SB_SLOT;
            uint32_t spA = sp + (uint32_t)((16*wm + ((mi & 1) << 3) + l7) * 144
                                           + (((mi >> 1) << 3)) * 2);
            uint32_t sbB = sb + (uint32_t)((((mi & 1) << 3) + l7) * 272
                                           + (32*wn + ((mi >> 1) << 3)) * 2);
#pragma unroll
            for (int kk = 0; kk < 4; kk++) {
                uint32_t afr[4];
                asm volatile(
                    "ldmatrix.sync.aligned.m8n8.x4.shared.b16 {%0,%1,%2,%3},[%4];\n"
                    : "=r"(afr[0]), "=r"(afr[1]), "=r"(afr[2]), "=r"(afr[3])
                    : "r"(spA + (uint32_t)(32 * kk)));
                uint32_t b[4];
                asm volatile(
                    "ldmatrix.sync.aligned.m8n8.x4.trans.shared.b16 {%0,%1,%2,%3},[%4];\n"
                    : "=r"(b[0]), "=r"(b[1]), "=r"(b[2]), "=r"(b[3])
                    : "r"(sbB + (uint32_t)(16 * kk * 272)));
                mma_fp16(acc[0], afr, b[0], b[1]);
                mma_fp16(acc[1], afr, b[2], b[3]);
                asm volatile(
                    "ldmatrix.sync.aligned.m8n8.x4.trans.shared.b16 {%0,%1,%2,%3},[%4];\n"
                    : "=r"(b[0]), "=r"(b[1]), "=r"(b[2]), "=r"(b[3])
                    : "r"(sbB + (uint32_t)(16 * kk * 272 + 32)));
                mma_fp16(acc[2], afr, b[0], b[1]);
                mma_fp16(acc[3], afr, b[2], b[3]);
            }
            MBAR_ARRIVE(mbE + 8*s);
            if (s == 3) fph ^= 1;
        }

        // ---- wait for producers' sden, then normalize + store ----
        asm volatile("bar.sync 1, 512;" ::: "memory");
        const int g = lane >> 2, t = lane & 3;
        int row0 = 16*wm + g;
        float inv0 = 1.0f / sden[row0];
        float inv1 = 1.0f / sden[row0 + 8];
#pragma unroll
        for (int nf = 0; nf < 4; nf++) {
            int col = 32*wn + 8*nf + 2*t;
            out[(size_t)(i0 + row0)     * FOUT + col    ] = acc[nf][0] * inv0;
            out[(size_t)(i0 + row0)     * FOUT + col + 1] = acc[nf][1] * inv0;
            out[(size_t)(i0 + row0 + 8) * FOUT + col    ] = acc[nf][2] * inv1;
            out[(size_t)(i0 + row0 + 8) * FOUT + col + 1] = acc[nf][3] * inv1;
        }
    }
}

// =====================================================================
extern "C" void kernel_launch(void* const* d_in, const int* in_sizes, int n_in,
                              void* d_out, int out_size)
{
    const float* h   = (const float*)d_in[0];   // [8192,256] f32
    const int*   adj = (const int*)  d_in[1];   // [8192,8192] i32
    const float* Wm  = (const float*)d_in[2];   // [256,128] f32
    const float* a   = (const float*)d_in[3];   // [256,1] f32
    float* out = (float*)d_out;                 // [8192,128] f32

    cudaFuncSetAttribute(gat_main_kernel,
                         cudaFuncAttributeMaxDynamicSharedMemorySize, DYN_SMEM);

    wh_gemm_kernel <<<256, 256>>>(h, Wm, a);
    gat_main_kernel<<<GRID_MAIN, 512, DYN_SMEM>>>(adj, out);
}